// round 5
// baseline (speedup 1.0000x reference)
#include <cuda_runtime.h>
#include <cuda_fp16.h>
#include <math.h>

// Problem constants: preds [8,4,256,256] f32, targets [8,256,256] i32.
#define B 8
#define H 256
#define W 256
#define NCLS 3              // classes 1..3
#define NCB 24              // cb = (cls-1)*8 + b
#define IMG 65536           // H*W
#define NPIX 524288         // B*H*W
#define RWIN 4              // window radius; certified exact when min <= 16
#define OOB 25.0f           // out-of-window / out-of-bounds distance^2 (>16)
#define NBLK2 512           // fused-kernel block count

// -------- scratch (__device__ globals; no runtime allocation) --------
__device__ __half2 d_g[NCB * IMG];   // per pixel: (gPos, gNeg) in {0,1,4,9,16,25}
__device__ unsigned d_mask[NCLS * B * H * 8];  // row bitmasks (exact fallback)
__device__ int   d_flag[NCB * W];    // per (cb, x): window not certified
__device__ float d_partial[3 * NBLK2];
__device__ int   d_cnt[3 * NBLK2];

// ---------------------------------------------------------------------
// Branchless windowed row distance^2 (radius 4).
// win bits 0..8 correspond to positions x-4 .. x+4 (bit 4 = x).
// Exact for d <= 4, else 25 (>16, never enters a certified min).
// ---------------------------------------------------------------------
__device__ __forceinline__ int win_d2_4(unsigned win) {
    unsigned t = win & 0x1Fu;                 // x-4..x
    int dl = __clz((t << 1) | 1u) - 26;       // 0..5
    unsigned t2 = (win >> 4) & 0x1Fu;         // x..x+4
    int dr = __ffs(t2 | 0x20u) - 1;           // 0..5
    int d = dl < dr ? dl : dr;
    return d * d;                              // <= 25
}

// ---------------------------------------------------------------------
// K1: warp-per-row. No smem, no __syncthreads. Each warp ballots its
// row into 8 register-resident words, every lane then builds 8 windowed
// distances (one per 32-x chunk) from registers via funnel shifts.
// Stores packed (P,N) half2 per pixel per class + masks for fallback.
// ---------------------------------------------------------------------
__global__ __launch_bounds__(256) void k1_rows(const int* __restrict__ tg) {
    int lane = threadIdx.x & 31;
    int wrp = threadIdx.x >> 5;
    int row = blockIdx.x * 8 + wrp;   // 0..2047 = b*256 + y
    if (blockIdx.x < NCB) d_flag[blockIdx.x * 256 + threadIdx.x] = 0;

    int tv[8];
#pragma unroll
    for (int c = 0; c < 8; ++c) tv[c] = tg[row * 256 + c * 32 + lane];
    int bb = row >> 8, y = row & 255;

#pragma unroll
    for (int cls = 1; cls <= NCLS; ++cls) {
        unsigned b[8];
#pragma unroll
        for (int c = 0; c < 8; ++c) {
            b[c] = __ballot_sync(0xFFFFFFFFu, tv[c] == cls);
            if (lane == c) d_mask[((cls - 1) * (B * H) + row) * 8 + c] = b[c];
        }
        __half2* dst = d_g + ((cls - 1) * 8 + bb) * IMG + y * 256;
#pragma unroll
        for (int c = 0; c < 8; ++c) {
            unsigned bp = (c > 0) ? b[c - 1] : 0u;
            unsigned bn = (c < 7) ? b[c + 1] : 0u;
            unsigned nbp = (c > 0) ? ~b[c - 1] : 0u;
            unsigned nbn = (c < 7) ? ~b[c + 1] : 0u;
            unsigned winP, winN;
            if (lane < 4) {
                winP = __funnelshift_r(bp, b[c], lane + 28);
                winN = __funnelshift_r(nbp, ~b[c], lane + 28);
            } else {
                winP = __funnelshift_r(b[c], bn, lane - 4);
                winN = __funnelshift_r(~b[c], nbn, lane - 4);
            }
            int p2 = win_d2_4(winP);
            int n2 = win_d2_4(winN);
            dst[c * 32 + lane] =
                __halves2half2(__float2half_rn((float)p2), __float2half_rn((float)n2));
        }
    }
}

// ---------------------------------------------------------------------
// K23 (fused): half2 (P,N) windowed column EDT + dmap + softmax + reduce.
// Grid: 8 b * 64 ytiles(4 rows) = 512 blocks, 256 threads (thread = x).
// Certified exact when windowed min <= 16 (else flag -> exact fallback).
// ---------------------------------------------------------------------
__global__ __launch_bounds__(256) void k23_fused(const float* __restrict__ preds) {
    int x = threadIdx.x;
    int b = blockIdx.x >> 6;
    int y0 = (blockIdx.x & 63) << 2;

    const __half2 HOOB = __float2half2_rn(OOB);
    float dmap[3][4];
    int cnt[3] = {0, 0, 0};

#pragma unroll
    for (int cls = 0; cls < 3; ++cls) {
        int cb = cls * 8 + b;
        const __half2* __restrict__ g = d_g + cb * IMG + x;
        __half2 v[2 * RWIN + 4];
#pragma unroll
        for (int r = 0; r < 2 * RWIN + 4; ++r) {
            int gy = y0 - RWIN + r;
            v[r] = (gy >= 0 && gy < H) ? g[gy << 8] : HOOB;
        }
        bool bad = false;
#pragma unroll
        for (int o = 0; o < 4; ++o) {
            __half2 m = v[o + RWIN];
#pragma unroll
            for (int dy = 1; dy <= RWIN; ++dy) {
                __half2 dd = __float2half2_rn((float)(dy * dy));
                m = __hmin2(m, __hadd2(v[o + RWIN - dy], dd));
                m = __hmin2(m, __hadd2(v[o + RWIN + dy], dd));
            }
            float mp = __low2float(m);
            float mn = __high2float(m);
            bad |= (mp > 16.0f) || (mn > 16.0f);
            bool pos = (__low2float(v[o + RWIN]) == 0.0f);
            dmap[cls][o] = pos ? (1.0f - sqrtf(mn)) : sqrtf(mp);
            cnt[cls] += pos ? 1 : 0;
        }
        if (bad) d_flag[cb * W + x] = 1;    // races benign (all write 1)
    }

    // softmax + dot with dmap
    float s[3] = {0.f, 0.f, 0.f};
    const float* pb = preds + b * (4 * IMG) + (y0 << 8) + x;
#pragma unroll
    for (int o = 0; o < 4; ++o) {
        const float* p = pb + (o << 8);
        float e0 = __expf(p[0]);
        float e1 = __expf(p[IMG]);
        float e2 = __expf(p[2 * IMG]);
        float e3 = __expf(p[3 * IMG]);
        float inv = 1.0f / (e0 + e1 + e2 + e3);
        s[0] += dmap[0][o] * (e1 * inv);
        s[1] += dmap[1][o] * (e2 * inv);
        s[2] += dmap[2][o] * (e3 * inv);
    }

    // block reduction
#pragma unroll
    for (int off = 16; off; off >>= 1) {
#pragma unroll
        for (int c = 0; c < 3; ++c) {
            s[c] += __shfl_down_sync(0xFFFFFFFFu, s[c], off);
            cnt[c] += __shfl_down_sync(0xFFFFFFFFu, cnt[c], off);
        }
    }
    __shared__ float sm[8][3];
    __shared__ int smc[8][3];
    int w = threadIdx.x >> 5;
    if ((threadIdx.x & 31) == 0) {
#pragma unroll
        for (int c = 0; c < 3; ++c) { sm[w][c] = s[c]; smc[w][c] = cnt[c]; }
    }
    __syncthreads();
    if (threadIdx.x < 3) {
        float t = 0.0f; int ci = 0;
#pragma unroll
        for (int i = 0; i < 8; ++i) { t += sm[i][threadIdx.x]; ci += smc[i][threadIdx.x]; }
        d_partial[threadIdx.x * NBLK2 + blockIdx.x] = t;
        d_cnt[threadIdx.x * NBLK2 + blockIdx.x] = ci;
    }
}

// ---------------------------------------------------------------------
// Exact reference rowdist (full scans) — fallback only.
// ---------------------------------------------------------------------
__device__ int rowdist_full(const unsigned* m, int x, bool inv) {
    int w = x >> 5, b = x & 31;
    unsigned mw = inv ? ~m[w] : m[w];
    unsigned u = mw & (0xFFFFFFFFu >> (31 - b));
    int dl;
    if (u) {
        dl = b - (31 - __clz(u));
    } else {
        dl = 512 + x + 1;
        for (int i = w - 1; i >= 0; --i) {
            unsigned vi = inv ? ~m[i] : m[i];
            if (vi) { dl = x - (i * 32 + 31 - __clz(vi)); break; }
        }
    }
    unsigned u2 = mw & (0xFFFFFFFFu << b);
    int dr;
    if (u2) {
        dr = (__ffs(u2) - 1) - b;
    } else {
        dr = 512 + 256 - x;
        for (int i = w + 1; i < 8; ++i) {
            unsigned vi = inv ? ~m[i] : m[i];
            if (vi) { dr = i * 32 + (__ffs(vi) - 1) - x; break; }
        }
    }
    return dl < dr ? dl : dr;
}

// Exact fallback for one flagged column: exact EDT from stored masks,
// bit-exact replication of the approximate (windowed, clamped) path,
// deterministic correction. Never executes on typical inputs.
__device__ void fix_column(int cb, int x, const float* preds, float* adj) {
    int cls = cb >> 3;      // 0-based
    int b = cb & 7;
    float gpe[256], gne[256];
    for (int y = 0; y < 256; ++y) {
        unsigned mw[8];
#pragma unroll
        for (int i = 0; i < 8; ++i)
            mw[i] = d_mask[(cls * (B * H) + b * 256 + y) * 8 + i];
        int dp = rowdist_full(mw, x, false);
        int dn = rowdist_full(mw, x, true);
        gpe[y] = (float)(dp * dp);
        gne[y] = (float)(dn * dn);
    }
    const __half2* g = d_g + cb * IMG + x;
    float delta = 0.0f;
    for (int y = 0; y < 256; ++y) {
        float mpE = 1e30f, mnE = 1e30f;
        for (int yp = 0; yp < 256; ++yp) {
            float dy2 = (float)((y - yp) * (y - yp));
            mpE = fminf(mpE, gpe[yp] + dy2);
            mnE = fminf(mnE, gne[yp] + dy2);
        }
        bool pos = (__low2float(g[y << 8]) == 0.0f);
        float exact = pos ? (1.0f - sqrtf(mnE)) : sqrtf(mpE);
        // replicate approximate path exactly (window +-4, OOB=25)
        float mpA = 1e30f, mnA = 1e30f;
        for (int dy = -RWIN; dy <= RWIN; ++dy) {
            int gy = y + dy;
            float Sp = OOB, Sn = OOB;
            if (gy >= 0 && gy < H) {
                __half2 gv = g[gy << 8];
                Sp = __low2float(gv);
                Sn = __high2float(gv);
            }
            float d2 = (float)(dy * dy);
            mpA = fminf(mpA, Sp + d2);
            mnA = fminf(mnA, Sn + d2);
        }
        float approx = pos ? (1.0f - sqrtf(mnA)) : sqrtf(mpA);
        if (exact != approx) {
            const float* p = preds + b * (4 * IMG) + (y << 8) + x;
            float e0 = __expf(p[0]);
            float e1 = __expf(p[IMG]);
            float e2 = __expf(p[2 * IMG]);
            float e3 = __expf(p[3 * IMG]);
            float inv = 1.0f / (e0 + e1 + e2 + e3);
            float pr = ((cls == 0) ? e1 : (cls == 1) ? e2 : e3) * inv;
            delta += (exact - approx) * pr;
        }
    }
    adj[cls] += delta;
}

// ---------------------------------------------------------------------
// K4: final deterministic reduction + fallback corrections + has/count.
// ---------------------------------------------------------------------
__global__ __launch_bounds__(256) void k4_final(const float* __restrict__ preds,
                                                float* __restrict__ out) {
    __shared__ float red[256];
    __shared__ float tot[3];
    __shared__ float ccnt[3];
    __shared__ int flagged;
    __shared__ float adj[3];
    int tid = threadIdx.x;
    for (int q = 0; q < 3; ++q) {
        red[tid] = d_partial[q * NBLK2 + tid] + d_partial[q * NBLK2 + 256 + tid];
        __syncthreads();
        for (int st = 128; st; st >>= 1) {
            if (tid < st) red[tid] += red[tid + st];
            __syncthreads();
        }
        if (tid == 0) tot[q] = red[0];
        __syncthreads();
    }
    for (int q = 0; q < 3; ++q) {
        red[tid] = (float)(d_cnt[q * NBLK2 + tid] + d_cnt[q * NBLK2 + 256 + tid]);
        __syncthreads();
        for (int st = 128; st; st >>= 1) {
            if (tid < st) red[tid] += red[tid + st];
            __syncthreads();
        }
        if (tid == 0) ccnt[q] = red[0];
        __syncthreads();
    }
    if (tid == 0) { flagged = 0; adj[0] = adj[1] = adj[2] = 0.0f; }
    __syncthreads();
    int f = 0;
    for (int i = tid; i < NCB * W; i += 256) f |= d_flag[i];
    if (f) atomicOr(&flagged, 1);
    __syncthreads();
    if (flagged && tid == 0) {
        for (int cb = 0; cb < NCB; ++cb)
            for (int x = 0; x < W; ++x)
                if (d_flag[cb * W + x]) fix_column(cb, x, preds, adj);
    }
    __syncthreads();
    if (tid == 0) {
        float total = 0.0f, count = 0.0f;
        for (int c = 0; c < 3; ++c) {
            if (ccnt[c] > 0.0f) {
                total += (tot[c] + adj[c]) * (1.0f / (float)NPIX);
                count += 1.0f;
            }
        }
        out[0] = (count > 0.0f) ? (total / count) : 0.0f;
    }
}

extern "C" void kernel_launch(void* const* d_in, const int* in_sizes, int n_in,
                              void* d_out, int out_size) {
    const float* preds = (const float*)d_in[0];
    const int* targets = (const int*)d_in[1];
    float* out = (float*)d_out;

    k1_rows<<<B * H / 8, 256>>>(targets);
    k23_fused<<<NBLK2, 256>>>(preds);
    k4_final<<<1, 256>>>(preds, out);
}

// round 6
// speedup vs baseline: 338.6856x; 338.6856x over previous
#include <cuda_runtime.h>
#include <cuda_fp16.h>
#include <math.h>

// Problem constants: preds [8,4,256,256] f32, targets [8,256,256] i32.
#define B 8
#define H 256
#define W 256
#define NCLS 3              // classes 1..3
#define NCB 24              // cb = (cls-1)*8 + b
#define IMG 65536           // H*W
#define NPIX 524288         // B*H*W
#define RWIN 6              // window radius; certified exact when min <= 36
#define THRESH 36.0f
#define OOB 49.0f           // out-of-window / out-of-bounds distance^2 (>36)
#define NBLK2 512           // fused-kernel block count

// -------- scratch (__device__ globals; no runtime allocation) --------
__device__ __half2 d_g[NCB * IMG];   // per pixel: (gPos, gNeg), ints {0..36, 49}
__device__ unsigned d_mask[NCLS * B * H * 8];  // row bitmasks (exact fallback)
__device__ int   d_flag[NCB * W];    // per (cb, x): window not certified
__device__ float d_partial[3 * NBLK2];
__device__ int   d_cnt[3 * NBLK2];

// ---------------------------------------------------------------------
// Branchless windowed row distance^2 (radius 6).
// win bits 0..12 correspond to positions x-6 .. x+6 (bit 6 = x).
// Exact for d <= 6, else 49 (>36, never enters a certified min).
// ---------------------------------------------------------------------
__device__ __forceinline__ int win_d2_6(unsigned win) {
    unsigned t = win & 0x7Fu;                 // x-6..x
    int dl = __clz((t << 1) | 1u) - 24;       // 0..7
    unsigned t2 = (win >> 6) & 0x7Fu;         // x..x+6
    int dr = __ffs(t2 | 0x80u) - 1;           // 0..7
    int d = dl < dr ? dl : dr;
    return d * d;                              // <= 49
}

// ---------------------------------------------------------------------
// K1: one warp per (row, class). No smem, no __syncthreads. Warp ballots
// its row into 8 register-resident words; every lane builds 8 windowed
// distances via funnel shifts. Stores packed (P,N) half2 + masks.
// Grid: 2048 rows * 3 classes / 8 warps = 768 blocks.
// ---------------------------------------------------------------------
__global__ __launch_bounds__(256) void k1_rows(const int* __restrict__ tg) {
    int lane = threadIdx.x & 31;
    int wrp = threadIdx.x >> 5;
    int g = blockIdx.x * 8 + wrp;      // 0..6143
    int cls = (g % 3) + 1;
    int row = g / 3;                   // 0..2047 = b*256 + y
    if (blockIdx.x < NCB) d_flag[blockIdx.x * 256 + threadIdx.x] = 0;

    int tv[8];
#pragma unroll
    for (int c = 0; c < 8; ++c) tv[c] = tg[row * 256 + c * 32 + lane];
    int bb = row >> 8, y = row & 255;

    unsigned b[8];
#pragma unroll
    for (int c = 0; c < 8; ++c) {
        b[c] = __ballot_sync(0xFFFFFFFFu, tv[c] == cls);
        if (lane == c) d_mask[((cls - 1) * (B * H) + row) * 8 + c] = b[c];
    }
    __half2* dst = d_g + ((cls - 1) * 8 + bb) * IMG + y * 256;
#pragma unroll
    for (int c = 0; c < 8; ++c) {
        unsigned bp = (c > 0) ? b[c - 1] : 0u;
        unsigned bn = (c < 7) ? b[c + 1] : 0u;
        unsigned nbp = (c > 0) ? ~b[c - 1] : 0u;
        unsigned nbn = (c < 7) ? ~b[c + 1] : 0u;
        unsigned winP, winN;
        if (lane < RWIN) {
            winP = __funnelshift_r(bp, b[c], lane + 32 - RWIN);
            winN = __funnelshift_r(nbp, ~b[c], lane + 32 - RWIN);
        } else {
            winP = __funnelshift_r(b[c], bn, lane - RWIN);
            winN = __funnelshift_r(~b[c], nbn, lane - RWIN);
        }
        int p2 = win_d2_6(winP);
        int n2 = win_d2_6(winN);
        dst[c * 32 + lane] =
            __halves2half2(__float2half_rn((float)p2), __float2half_rn((float)n2));
    }
}

// ---------------------------------------------------------------------
// K23 (fused): half2 (P,N) windowed column EDT + dmap + softmax + reduce.
// Grid: 8 b * 64 ytiles(4 rows) = 512 blocks, 256 threads (thread = x).
// Certified exact when windowed min <= 36 (else flag -> exact fallback).
// ---------------------------------------------------------------------
__global__ __launch_bounds__(256) void k23_fused(const float* __restrict__ preds) {
    int x = threadIdx.x;
    int b = blockIdx.x >> 6;
    int y0 = (blockIdx.x & 63) << 2;

    const __half2 HOOB = __float2half2_rn(OOB);
    float dmap[3][4];
    int cnt[3] = {0, 0, 0};

#pragma unroll
    for (int cls = 0; cls < 3; ++cls) {
        int cb = cls * 8 + b;
        const __half2* __restrict__ g = d_g + cb * IMG + x;
        __half2 v[2 * RWIN + 4];
#pragma unroll
        for (int r = 0; r < 2 * RWIN + 4; ++r) {
            int gy = y0 - RWIN + r;
            v[r] = (gy >= 0 && gy < H) ? g[gy << 8] : HOOB;
        }
        bool bad = false;
#pragma unroll
        for (int o = 0; o < 4; ++o) {
            __half2 m = v[o + RWIN];
#pragma unroll
            for (int dy = 1; dy <= RWIN; ++dy) {
                __half2 dd = __float2half2_rn((float)(dy * dy));
                m = __hmin2(m, __hadd2(v[o + RWIN - dy], dd));
                m = __hmin2(m, __hadd2(v[o + RWIN + dy], dd));
            }
            float mp = __low2float(m);
            float mn = __high2float(m);
            bad |= (mp > THRESH) || (mn > THRESH);
            bool pos = (__low2float(v[o + RWIN]) == 0.0f);
            dmap[cls][o] = pos ? (1.0f - sqrtf(mn)) : sqrtf(mp);
            cnt[cls] += pos ? 1 : 0;
        }
        if (bad) d_flag[cb * W + x] = 1;    // races benign (all write 1)
    }

    // softmax + dot with dmap
    float s[3] = {0.f, 0.f, 0.f};
    const float* pb = preds + b * (4 * IMG) + (y0 << 8) + x;
#pragma unroll
    for (int o = 0; o < 4; ++o) {
        const float* p = pb + (o << 8);
        float e0 = __expf(p[0]);
        float e1 = __expf(p[IMG]);
        float e2 = __expf(p[2 * IMG]);
        float e3 = __expf(p[3 * IMG]);
        float inv = 1.0f / (e0 + e1 + e2 + e3);
        s[0] += dmap[0][o] * (e1 * inv);
        s[1] += dmap[1][o] * (e2 * inv);
        s[2] += dmap[2][o] * (e3 * inv);
    }

    // block reduction
#pragma unroll
    for (int off = 16; off; off >>= 1) {
#pragma unroll
        for (int c = 0; c < 3; ++c) {
            s[c] += __shfl_down_sync(0xFFFFFFFFu, s[c], off);
            cnt[c] += __shfl_down_sync(0xFFFFFFFFu, cnt[c], off);
        }
    }
    __shared__ float sm[8][3];
    __shared__ int smc[8][3];
    int w = threadIdx.x >> 5;
    if ((threadIdx.x & 31) == 0) {
#pragma unroll
        for (int c = 0; c < 3; ++c) { sm[w][c] = s[c]; smc[w][c] = cnt[c]; }
    }
    __syncthreads();
    if (threadIdx.x < 3) {
        float t = 0.0f; int ci = 0;
#pragma unroll
        for (int i = 0; i < 8; ++i) { t += sm[i][threadIdx.x]; ci += smc[i][threadIdx.x]; }
        d_partial[threadIdx.x * NBLK2 + blockIdx.x] = t;
        d_cnt[threadIdx.x * NBLK2 + blockIdx.x] = ci;
    }
}

// ---------------------------------------------------------------------
// Exact reference rowdist (full scans) — fallback only.
// ---------------------------------------------------------------------
__device__ int rowdist_full(const unsigned* m, int x, bool inv) {
    int w = x >> 5, b = x & 31;
    unsigned mw = inv ? ~m[w] : m[w];
    unsigned u = mw & (0xFFFFFFFFu >> (31 - b));
    int dl;
    if (u) {
        dl = b - (31 - __clz(u));
    } else {
        dl = 512 + x + 1;
        for (int i = w - 1; i >= 0; --i) {
            unsigned vi = inv ? ~m[i] : m[i];
            if (vi) { dl = x - (i * 32 + 31 - __clz(vi)); break; }
        }
    }
    unsigned u2 = mw & (0xFFFFFFFFu << b);
    int dr;
    if (u2) {
        dr = (__ffs(u2) - 1) - b;
    } else {
        dr = 512 + 256 - x;
        for (int i = w + 1; i < 8; ++i) {
            unsigned vi = inv ? ~m[i] : m[i];
            if (vi) { dr = i * 32 + (__ffs(vi) - 1) - x; break; }
        }
    }
    return dl < dr ? dl : dr;
}

// ---------------------------------------------------------------------
// Block-cooperative exact fallback for one flagged column (all 256
// threads participate; thread y handles row y). Exact EDT from stored
// masks; bit-exact replication of the approximate (windowed, clamped)
// path; deterministic tree-reduced correction. ~3us per flagged column.
// ---------------------------------------------------------------------
__device__ void fix_column_coop(int cb, int x, const float* __restrict__ preds,
                                float* adj, float* red) {
    int cls = cb >> 3;      // 0-based
    int b = cb & 7;
    int y = threadIdx.x;
    __shared__ float gpe[256], gne[256];
    {
        unsigned mw[8];
#pragma unroll
        for (int i = 0; i < 8; ++i)
            mw[i] = d_mask[(cls * (B * H) + b * 256 + y) * 8 + i];
        int dp = rowdist_full(mw, x, false);
        int dn = rowdist_full(mw, x, true);
        gpe[y] = (float)(dp * dp);
        gne[y] = (float)(dn * dn);
    }
    __syncthreads();
    const __half2* g = d_g + cb * IMG + x;
    float mpE = 1e30f, mnE = 1e30f;
    for (int yp = 0; yp < 256; ++yp) {
        float dy2 = (float)((y - yp) * (y - yp));
        mpE = fminf(mpE, gpe[yp] + dy2);
        mnE = fminf(mnE, gne[yp] + dy2);
    }
    bool pos = (gpe[y] == 0.0f);
    float exact = pos ? (1.0f - sqrtf(mnE)) : sqrtf(mpE);
    // replicate the approximate path exactly (window +-RWIN, clamps)
    float mpA = 1e30f, mnA = 1e30f;
#pragma unroll
    for (int dy = -RWIN; dy <= RWIN; ++dy) {
        int gy = y + dy;
        float Sp = OOB, Sn = OOB;
        if (gy >= 0 && gy < H) {
            __half2 gv = g[gy << 8];
            Sp = __low2float(gv);
            Sn = __high2float(gv);
        }
        float d2 = (float)(dy * dy);
        mpA = fminf(mpA, Sp + d2);
        mnA = fminf(mnA, Sn + d2);
    }
    float approx = pos ? (1.0f - sqrtf(mnA)) : sqrtf(mpA);
    float delta = 0.0f;
    if (exact != approx) {
        const float* p = preds + b * (4 * IMG) + (y << 8) + x;
        float e0 = __expf(p[0]);
        float e1 = __expf(p[IMG]);
        float e2 = __expf(p[2 * IMG]);
        float e3 = __expf(p[3 * IMG]);
        float inv = 1.0f / (e0 + e1 + e2 + e3);
        float pr = ((cls == 0) ? e1 : (cls == 1) ? e2 : e3) * inv;
        delta = (exact - approx) * pr;
    }
    __syncthreads();
    red[y] = delta;
    __syncthreads();
    for (int st = 128; st; st >>= 1) {
        if (y < st) red[y] += red[y + st];
        __syncthreads();
    }
    if (y == 0) adj[cls] += red[0];
    __syncthreads();
}

// ---------------------------------------------------------------------
// K4: final deterministic reduction + fallback corrections + has/count.
// ---------------------------------------------------------------------
__global__ __launch_bounds__(256) void k4_final(const float* __restrict__ preds,
                                                float* __restrict__ out) {
    __shared__ float red[256];
    __shared__ float tot[3];
    __shared__ float ccnt[3];
    __shared__ int flagged;
    __shared__ float adj[3];
    int tid = threadIdx.x;
    for (int q = 0; q < 3; ++q) {
        red[tid] = d_partial[q * NBLK2 + tid] + d_partial[q * NBLK2 + 256 + tid];
        __syncthreads();
        for (int st = 128; st; st >>= 1) {
            if (tid < st) red[tid] += red[tid + st];
            __syncthreads();
        }
        if (tid == 0) tot[q] = red[0];
        __syncthreads();
    }
    for (int q = 0; q < 3; ++q) {
        red[tid] = (float)(d_cnt[q * NBLK2 + tid] + d_cnt[q * NBLK2 + 256 + tid]);
        __syncthreads();
        for (int st = 128; st; st >>= 1) {
            if (tid < st) red[tid] += red[tid + st];
            __syncthreads();
        }
        if (tid == 0) ccnt[q] = red[0];
        __syncthreads();
    }
    if (tid == 0) { flagged = 0; adj[0] = adj[1] = adj[2] = 0.0f; }
    __syncthreads();
    int f = 0;
    for (int i = tid; i < NCB * W; i += 256) f |= d_flag[i];
    if (f) atomicOr(&flagged, 1);
    __syncthreads();
    if (flagged) {
        for (int i = 0; i < NCB * W; ++i) {
            if (d_flag[i]) fix_column_coop(i >> 8, i & 255, preds, adj, red);
        }
    }
    __syncthreads();
    if (tid == 0) {
        float total = 0.0f, count = 0.0f;
        for (int c = 0; c < 3; ++c) {
            if (ccnt[c] > 0.0f) {
                total += (tot[c] + adj[c]) * (1.0f / (float)NPIX);
                count += 1.0f;
            }
        }
        out[0] = (count > 0.0f) ? (total / count) : 0.0f;
    }
}

extern "C" void kernel_launch(void* const* d_in, const int* in_sizes, int n_in,
                              void* d_out, int out_size) {
    const float* preds = (const float*)d_in[0];
    const int* targets = (const int*)d_in[1];
    float* out = (float*)d_out;

    k1_rows<<<B * H * NCLS / 8, 256>>>(targets);
    k23_fused<<<NBLK2, 256>>>(preds);
    k4_final<<<1, 256>>>(preds, out);
}